// round 10
// baseline (speedup 1.0000x reference)
#include <cuda_runtime.h>
#include <cstdint>
#include <math_constants.h>

#define NN   1024
#define BB   128
#define SPLITK 16
#define KS   (NN / SPLITK)   // 64 k per block == smem depth (single shot)
#define BM   64              // b tile
#define BN   128             // j tile
#define XS_STRIDE 68
#define NT   512             // 16 warps

#define XS_FLOATS (KS * XS_STRIDE)            // 4352
#define SMEM_BYTES ((XS_FLOATS + KS * BN) * 4)  // 17408 + 32768 = 50176

// split-K partials: [SPLITK][BB][NN] = 8 MB
__device__ float g_partials[SPLITK * BB * NN];
// opaque -1.0f so ptxas cannot fold the FFMA back into FADD
__device__ float g_negone = -1.0f;

__device__ __forceinline__ void cp_async16(uint32_t dst_smem, const void* src) {
    asm volatile("cp.async.cg.shared.global [%0], [%1], 16;\n"
                 :: "r"(dst_smem), "l"(src));
}
__device__ __forceinline__ void cp_commit() {
    asm volatile("cp.async.commit_group;\n" ::: "memory");
}
__device__ __forceinline__ void cp_wait0() {
    asm volatile("cp.async.wait_group 0;\n" ::: "memory");
}

__global__ void __launch_bounds__(NT, 2)
tropical_main(const float* __restrict__ x,
              const float* __restrict__ w)
{
    extern __shared__ float smem[];
    float* xs = smem;                 // [KS][XS_STRIDE], transposed x: [k][b]
    float* ws = smem + XS_FLOATS;     // [KS][BN],        natural w:   [k][j]

    const int tid = threadIdx.x;
    const int tx  = tid & 31;        // j group (0..31)
    const int ty  = tid >> 5;        // b group / warp id (0..15)
    const int j0  = blockIdx.x * BN;
    const int b0  = blockIdx.y * BM;
    const int k0  = blockIdx.z * KS;

    // x load mapping: 2 float4 per thread (64 b-rows x 64 k)
    const int xb  = tid >> 3;              // 0..63
    const int xk4 = (tid & 7) << 2;        // 0..28 step 4 (+32 for h=1)
    // ws load mapping: 4 cp16 per thread (64 rows x 128 j)
    const int wrow = tid >> 5;             // 0..15 (+16h)
    const int wc4  = (tid & 31) << 2;      // 0..124 step 4

    const float negone = g_negone;         // runtime value -> real FFMA

    // ---- single-shot prologue: all 64 k into smem ----
    #pragma unroll
    for (int h = 0; h < 2; h++) {
        const int kk = 32 * h + xk4;
        float4 xr = *reinterpret_cast<const float4*>(&x[(b0 + xb) * NN + k0 + kk]);
        xs[(kk + 0) * XS_STRIDE + xb] = xr.x;
        xs[(kk + 1) * XS_STRIDE + xb] = xr.y;
        xs[(kk + 2) * XS_STRIDE + xb] = xr.z;
        xs[(kk + 3) * XS_STRIDE + xb] = xr.w;
    }
    #pragma unroll
    for (int h = 0; h < 4; h++) {
        const int kr = wrow + 16 * h;
        uint32_t d = (uint32_t)__cvta_generic_to_shared(&ws[kr * BN + wc4]);
        cp_async16(d, &w[(k0 + kr) * NN + j0 + wc4]);
    }
    cp_commit();

    float acc[4][4];
    #pragma unroll
    for (int r = 0; r < 4; r++)
        #pragma unroll
        for (int c = 0; c < 4; c++)
            acc[r][c] = -CUDART_INF_F;

    cp_wait0();
    __syncthreads();                 // the only block-wide sync

    const int jq = tx << 2;
    const int bq = ty << 2;

    // ---- straight 64-step compute ----
    #pragma unroll 8
    for (int k = 0; k < KS; k++) {
        float4 xv = *reinterpret_cast<const float4*>(&xs[k * XS_STRIDE + bq]); // warp bcast
        float4 wv = *reinterpret_cast<const float4*>(&ws[k * BN + jq]);
        float xr4[4] = {xv.x, xv.y, xv.z, xv.w};
        float wl[4]  = {wv.x, wv.y, wv.z, wv.w};
        #pragma unroll
        for (int r = 0; r < 4; r++)
            #pragma unroll
            for (int c = 0; c < 4; c++)
                acc[r][c] = fmaxf(acc[r][c], __fmaf_rn(wl[c], negone, xr4[r]));
    }

    // ---- write partials ----
    float* p = &g_partials[blockIdx.z * (BB * NN)];
    #pragma unroll
    for (int r = 0; r < 4; r++) {
        float4 o;
        o.x = acc[r][0]; o.y = acc[r][1]; o.z = acc[r][2]; o.w = acc[r][3];
        *reinterpret_cast<float4*>(&p[(b0 + bq + r) * NN + j0 + jq]) = o;
    }
}

__global__ void __launch_bounds__(256, 8)
tropical_reduce(const float* __restrict__ bias,
                float* __restrict__ out)
{
    const int i = (blockIdx.x * 256 + threadIdx.x) << 1;
    float2 m = *reinterpret_cast<const float2*>(&g_partials[i]);
    #pragma unroll
    for (int s = 1; s < SPLITK; s++) {
        float2 q = *reinterpret_cast<const float2*>(&g_partials[s * (BB * NN) + i]);
        m.x = fmaxf(m.x, q.x);
        m.y = fmaxf(m.y, q.y);
    }
    const int j = i & (NN - 1);
    float2 bv = *reinterpret_cast<const float2*>(&bias[j]);
    float2 o;
    o.x = m.x + bv.x;
    o.y = m.y + bv.y;
    *reinterpret_cast<float2*>(&out[i]) = o;
}

extern "C" void kernel_launch(void* const* d_in, const int* in_sizes, int n_in,
                              void* d_out, int out_size) {
    const float* x    = (const float*)d_in[0];   // [128, 1024]
    const float* wgt  = (const float*)d_in[1];   // [1024, 1024]
    const float* bias = (const float*)d_in[2];   // [1024]
    float* out = (float*)d_out;                  // [128, 1024]

    // >48KB dynamic smem needs the opt-in attribute (non-stream API, capture-safe)
    cudaFuncSetAttribute(tropical_main,
                         cudaFuncAttributeMaxDynamicSharedMemorySize, SMEM_BYTES);

    dim3 grid(NN / BN, BB / BM, SPLITK);         // (8, 2, 16) = 256 blocks
    tropical_main<<<grid, NT, SMEM_BYTES>>>(x, wgt);

    const int total = BB * NN;                   // 131072
    tropical_reduce<<<total / 2 / 256, 256>>>(bias, out);   // 256 blocks
}

// round 11
// speedup vs baseline: 1.0016x; 1.0016x over previous
#include <cuda_runtime.h>
#include <cstdint>
#include <math_constants.h>

#define NN   1024
#define BB   128
#define SPLITK 16
#define KS   (NN / SPLITK)   // 64 k per block
#define BM   64              // b tile
#define BN   128             // j tile
#define XS_STRIDE 68
#define NT   512             // 16 warps

#define XS_FLOATS (KS * XS_STRIDE)               // 64 * 68 = 4352
#define SMEM_BYTES ((XS_FLOATS + KS * BN) * 4)   // 17408 + 32768 = 50176

// split-K partials: [SPLITK][BB][NN] = 8 MB
__device__ float g_partials[SPLITK * BB * NN];
// opaque -1.0f so ptxas cannot fold the FFMA back into FADD
__device__ float g_negone = -1.0f;

__device__ __forceinline__ void cp_async16(uint32_t dst_smem, const void* src) {
    asm volatile("cp.async.cg.shared.global [%0], [%1], 16;\n"
                 :: "r"(dst_smem), "l"(src));
}
__device__ __forceinline__ void cp_commit() {
    asm volatile("cp.async.commit_group;\n" ::: "memory");
}
__device__ __forceinline__ void cp_wait1() {
    asm volatile("cp.async.wait_group 1;\n" ::: "memory");
}
__device__ __forceinline__ void cp_wait0() {
    asm volatile("cp.async.wait_group 0;\n" ::: "memory");
}

__global__ void __launch_bounds__(NT, 2)
tropical_main(const float* __restrict__ x,
              const float* __restrict__ w)
{
    extern __shared__ float smem[];
    float* xs = smem;                 // [KS][XS_STRIDE] transposed x: [k][b]
    float* ws = smem + XS_FLOATS;     // [KS][BN]        natural w:   [k][j]

    const int tid = threadIdx.x;
    const int tx  = tid & 31;        // j group (0..31)
    const int ty  = tid >> 5;        // b group / warp id (0..15)
    const int j0  = blockIdx.x * BN;
    const int b0  = blockIdx.y * BM;
    const int k0  = blockIdx.z * KS;

    // ws load mapping: per half-chunk, 2 cp16 per thread (32 rows x 128 j)
    const int wrow = tid >> 5;             // 0..15 (+16)
    const int wc4  = (tid & 31) << 2;      // 0..124 step 4
    // x load mapping: 2 float4 per thread (64 b-rows x 64 k)
    const int xb  = tid >> 3;              // 0..63
    const int xk4 = (tid & 7) << 2;        // 0..28 step 4 (+32)

    const float negone = g_negone;         // runtime value -> real FFMA

    // ---- issue ALL w loads first: two commit groups (k 0-31, k 32-63) ----
    #pragma unroll
    for (int h = 0; h < 2; h++) {
        const int kr = wrow + 16 * h;
        uint32_t d = (uint32_t)__cvta_generic_to_shared(&ws[kr * BN + wc4]);
        cp_async16(d, &w[(k0 + kr) * NN + j0 + wc4]);
    }
    cp_commit();                           // group 0: k 0..31
    #pragma unroll
    for (int h = 0; h < 2; h++) {
        const int kr = 32 + wrow + 16 * h;
        uint32_t d = (uint32_t)__cvta_generic_to_shared(&ws[kr * BN + wc4]);
        cp_async16(d, &w[(k0 + kr) * NN + j0 + wc4]);
    }
    cp_commit();                           // group 1: k 32..63

    // ---- stage all x (LDG -> STS), overlapping the cp.async traffic ----
    #pragma unroll
    for (int h = 0; h < 2; h++) {
        const int kk = 32 * h + xk4;
        float4 xr = *reinterpret_cast<const float4*>(&x[(b0 + xb) * NN + k0 + kk]);
        xs[(kk + 0) * XS_STRIDE + xb] = xr.x;
        xs[(kk + 1) * XS_STRIDE + xb] = xr.y;
        xs[(kk + 2) * XS_STRIDE + xb] = xr.z;
        xs[(kk + 3) * XS_STRIDE + xb] = xr.w;
    }

    float acc[4][4];
    #pragma unroll
    for (int r = 0; r < 4; r++)
        #pragma unroll
        for (int c = 0; c < 4; c++)
            acc[r][c] = -CUDART_INF_F;

    const int jq = tx << 2;
    const int bq = ty << 2;

    // ---- half 1: k 0..31 (group 1 still in flight) ----
    cp_wait1();
    __syncthreads();
    #pragma unroll
    for (int k = 0; k < 32; k++) {
        float4 xv = *reinterpret_cast<const float4*>(&xs[k * XS_STRIDE + bq]);  // bcast
        float4 wv = *reinterpret_cast<const float4*>(&ws[k * BN + jq]);
        float xr4[4] = {xv.x, xv.y, xv.z, xv.w};
        float wl[4]  = {wv.x, wv.y, wv.z, wv.w};
        #pragma unroll
        for (int r = 0; r < 4; r++)
            #pragma unroll
            for (int c = 0; c < 4; c++)
                acc[r][c] = fmaxf(acc[r][c], __fmaf_rn(wl[c], negone, xr4[r]));
    }

    // ---- half 2: k 32..63 ----
    cp_wait0();
    __syncthreads();
    #pragma unroll
    for (int k = 32; k < 64; k++) {
        float4 xv = *reinterpret_cast<const float4*>(&xs[k * XS_STRIDE + bq]);
        float4 wv = *reinterpret_cast<const float4*>(&ws[k * BN + jq]);
        float xr4[4] = {xv.x, xv.y, xv.z, xv.w};
        float wl[4]  = {wv.x, wv.y, wv.z, wv.w};
        #pragma unroll
        for (int r = 0; r < 4; r++)
            #pragma unroll
            for (int c = 0; c < 4; c++)
                acc[r][c] = fmaxf(acc[r][c], __fmaf_rn(wl[c], negone, xr4[r]));
    }

    // ---- write partials (plain STG.128) ----
    float* p = &g_partials[blockIdx.z * (BB * NN)];
    #pragma unroll
    for (int r = 0; r < 4; r++) {
        float4 o;
        o.x = acc[r][0]; o.y = acc[r][1]; o.z = acc[r][2]; o.w = acc[r][3];
        *reinterpret_cast<float4*>(&p[(b0 + bq + r) * NN + j0 + jq]) = o;
    }
}

__global__ void __launch_bounds__(256, 8)
tropical_reduce(const float* __restrict__ bias,
                float* __restrict__ out)
{
    // 512 blocks x 256 threads, 1 float per thread -> ~3.5 blocks/SM of pure TLP
    const int i = blockIdx.x * 256 + threadIdx.x;
    float m = g_partials[i];
    #pragma unroll
    for (int s = 1; s < SPLITK; s++)
        m = fmaxf(m, g_partials[s * (BB * NN) + i]);
    out[i] = m + bias[i & (NN - 1)];
}

extern "C" void kernel_launch(void* const* d_in, const int* in_sizes, int n_in,
                              void* d_out, int out_size) {
    const float* x    = (const float*)d_in[0];   // [128, 1024]
    const float* wgt  = (const float*)d_in[1];   // [1024, 1024]
    const float* bias = (const float*)d_in[2];   // [1024]
    float* out = (float*)d_out;                  // [128, 1024]

    cudaFuncSetAttribute(tropical_main,
                         cudaFuncAttributeMaxDynamicSharedMemorySize, SMEM_BYTES);

    dim3 grid(NN / BN, BB / BM, SPLITK);         // (8, 2, 16) = 256 blocks
    tropical_main<<<grid, NT, SMEM_BYTES>>>(x, wgt);

    const int total = BB * NN;                   // 131072
    tropical_reduce<<<total / 256, 256>>>(bias, out);   // 512 blocks
}

// round 13
// speedup vs baseline: 1.0491x; 1.0475x over previous
#include <cuda_runtime.h>
#include <cstdint>
#include <math_constants.h>

#define NN   1024
#define BB   128
#define SPLITK 16
#define KS   (NN / SPLITK)   // 64 k per block
#define BK   32              // k chunk in smem
#define BM   64              // b tile
#define BN   128             // j tile
#define NT   512             // 16 warps
#define XD_STRIDE 132        // duplicated row: 128 floats + 4 pad (528B, 16B-aligned)

#define XS_FLOATS (BK * XD_STRIDE)                 // 32*132 = 4224
#define WS_FLOATS (2 * BK * BN)                    // double-buffered w: 8192
#define SMEM_BYTES ((XS_FLOATS + WS_FLOATS) * 4)   // 16896 + 32768 = 49664

// split-K partials (min of (w - x)): [SPLITK][BB][NN] = 8 MB
__device__ float g_partials[SPLITK * BB * NN];

__device__ __forceinline__ void cp_async16(uint32_t dst_smem, const void* src) {
    asm volatile("cp.async.cg.shared.global [%0], [%1], 16;\n"
                 :: "r"(dst_smem), "l"(src));
}
__device__ __forceinline__ void cp_commit() {
    asm volatile("cp.async.commit_group;\n" ::: "memory");
}
__device__ __forceinline__ void cp_wait0() {
    asm volatile("cp.async.wait_group 0;\n" ::: "memory");
}

// packed f32x2 add: two independent rn adds in one instruction (fma pipe)
__device__ __forceinline__ unsigned long long add_f32x2(unsigned long long a,
                                                        unsigned long long b) {
    unsigned long long d;
    asm("add.rn.f32x2 %0, %1, %2;" : "=l"(d) : "l"(a), "l"(b));
    return d;
}
// unpack 64-bit pair -> two f32 regs (register aliasing, pure)
__device__ __forceinline__ void unpack2(unsigned long long v, float& lo, float& hi) {
    asm("mov.b64 {%0, %1}, %2;" : "=f"(lo), "=f"(hi) : "l"(v));
}
// ld.shared.v2.u64 — VOLATILE + memory clobber: these read smem that plain C
// stores mutate between the two chunk loops; without the clobber ptxas CSE'd
// the chunk-1 loads (the R12 correctness bug).
__device__ __forceinline__ void lds_v2u64(const float* p,
                                          unsigned long long& a, unsigned long long& b) {
    asm volatile("ld.shared.v2.u64 {%0, %1}, [%2];"
                 : "=l"(a), "=l"(b)
                 : "l"(__cvta_generic_to_shared(p))
                 : "memory");
}

__global__ void __launch_bounds__(NT, 2)
tropical_main(const float* __restrict__ x,
              const float* __restrict__ w)
{
    extern __shared__ float smem[];
    float* xs = smem;                 // [BK][XD_STRIDE]: duplicated NEGATED x pairs
    float* ws = smem + XS_FLOATS;     // [2][BK][BN]: natural w

    const int tid = threadIdx.x;
    const int tx  = tid & 31;        // j group (0..31)
    const int ty  = tid >> 5;        // b group / warp id (0..15)
    const int j0  = blockIdx.x * BN;
    const int b0  = blockIdx.y * BM;
    const int k0  = blockIdx.z * KS;

    // x load mapping: 1 float4 per thread per chunk (64 b-rows x 32 k)
    const int xb  = tid >> 3;              // 0..63
    const int xk4 = (tid & 7) << 2;        // 0..28 step 4
    // ws load mapping: 2 cp16 per thread per chunk (32 rows x 128 j)
    const int wrow = tid >> 5;             // 0..15 (+16)
    const int wc4  = (tid & 31) << 2;      // 0..124 step 4

    float acc[4][4];                        // running MIN of (w - x)
    #pragma unroll
    for (int r = 0; r < 4; r++)
        #pragma unroll
        for (int c = 0; c < 4; c++)
            acc[r][c] = CUDART_INF_F;

    // ---- prologue: chunk 0 -> xs(dup,neg) + ws[0] ----
    {
        float4 xr = *reinterpret_cast<const float4*>(&x[(b0 + xb) * NN + k0 + xk4]);
        float2* xrow;
        xrow = reinterpret_cast<float2*>(&xs[(xk4 + 0) * XD_STRIDE + 2 * xb]);
        *xrow = make_float2(-xr.x, -xr.x);
        xrow = reinterpret_cast<float2*>(&xs[(xk4 + 1) * XD_STRIDE + 2 * xb]);
        *xrow = make_float2(-xr.y, -xr.y);
        xrow = reinterpret_cast<float2*>(&xs[(xk4 + 2) * XD_STRIDE + 2 * xb]);
        *xrow = make_float2(-xr.z, -xr.z);
        xrow = reinterpret_cast<float2*>(&xs[(xk4 + 3) * XD_STRIDE + 2 * xb]);
        *xrow = make_float2(-xr.w, -xr.w);
        #pragma unroll
        for (int h = 0; h < 2; h++) {
            const int kr = wrow + 16 * h;
            uint32_t d = (uint32_t)__cvta_generic_to_shared(&ws[kr * BN + wc4]);
            cp_async16(d, &w[(k0 + kr) * NN + j0 + wc4]);
        }
        cp_commit();
        cp_wait0();
        __syncthreads();
    }

    // ---- prefetch chunk 1: x into regs, ws via cp.async ----
    float4 xn;
    {
        const int kb = k0 + BK;
        xn = *reinterpret_cast<const float4*>(&x[(b0 + xb) * NN + kb + xk4]);
        #pragma unroll
        for (int h = 0; h < 2; h++) {
            const int kr = wrow + 16 * h;
            uint32_t d = (uint32_t)__cvta_generic_to_shared(&ws[BK * BN + kr * BN + wc4]);
            cp_async16(d, &w[(kb + kr) * NN + j0 + wc4]);
        }
        cp_commit();
    }

    const int jq  = tx << 2;   // 0..124 step 4
    const int bq2 = ty << 3;   // duplicated-row float offset (32B aligned)

    // ---- compute chunk 0 ----
    #pragma unroll
    for (int k = 0; k < BK; k++) {
        unsigned long long xp0, xp1, xp2, xp3, wp0, wp1;
        lds_v2u64(&xs[k * XD_STRIDE + bq2],     xp0, xp1);   // (-x0,-x0),(-x1,-x1)
        lds_v2u64(&xs[k * XD_STRIDE + bq2 + 4], xp2, xp3);   // (-x2,-x2),(-x3,-x3)
        lds_v2u64(&ws[k * BN + jq],             wp0, wp1);   // (w0,w1),(w2,w3)
        unsigned long long xp[4] = {xp0, xp1, xp2, xp3};
        #pragma unroll
        for (int r = 0; r < 4; r++) {
            float d0, d1, d2, d3;
            unpack2(add_f32x2(wp0, xp[r]), d0, d1);
            unpack2(add_f32x2(wp1, xp[r]), d2, d3);
            acc[r][0] = fminf(acc[r][0], d0);
            acc[r][1] = fminf(acc[r][1], d1);
            acc[r][2] = fminf(acc[r][2], d2);
            acc[r][3] = fminf(acc[r][3], d3);
        }
    }

    // ---- drain readers, stage x chunk 1 (dup + neg) ----
    __syncthreads();
    {
        float2* xrow;
        xrow = reinterpret_cast<float2*>(&xs[(xk4 + 0) * XD_STRIDE + 2 * xb]);
        *xrow = make_float2(-xn.x, -xn.x);
        xrow = reinterpret_cast<float2*>(&xs[(xk4 + 1) * XD_STRIDE + 2 * xb]);
        *xrow = make_float2(-xn.y, -xn.y);
        xrow = reinterpret_cast<float2*>(&xs[(xk4 + 2) * XD_STRIDE + 2 * xb]);
        *xrow = make_float2(-xn.z, -xn.z);
        xrow = reinterpret_cast<float2*>(&xs[(xk4 + 3) * XD_STRIDE + 2 * xb]);
        *xrow = make_float2(-xn.w, -xn.w);
    }
    cp_wait0();
    __syncthreads();

    // ---- compute chunk 1 ----
    #pragma unroll
    for (int k = 0; k < BK; k++) {
        unsigned long long xp0, xp1, xp2, xp3, wp0, wp1;
        lds_v2u64(&xs[k * XD_STRIDE + bq2],     xp0, xp1);
        lds_v2u64(&xs[k * XD_STRIDE + bq2 + 4], xp2, xp3);
        lds_v2u64(&ws[BK * BN + k * BN + jq],   wp0, wp1);
        unsigned long long xp[4] = {xp0, xp1, xp2, xp3};
        #pragma unroll
        for (int r = 0; r < 4; r++) {
            float d0, d1, d2, d3;
            unpack2(add_f32x2(wp0, xp[r]), d0, d1);
            unpack2(add_f32x2(wp1, xp[r]), d2, d3);
            acc[r][0] = fminf(acc[r][0], d0);
            acc[r][1] = fminf(acc[r][1], d1);
            acc[r][2] = fminf(acc[r][2], d2);
            acc[r][3] = fminf(acc[r][3], d3);
        }
    }

    // ---- write partials: min of (w - x) ----
    float* p = &g_partials[blockIdx.z * (BB * NN)];
    const int bq = ty << 2;
    #pragma unroll
    for (int r = 0; r < 4; r++) {
        float4 o;
        o.x = acc[r][0]; o.y = acc[r][1]; o.z = acc[r][2]; o.w = acc[r][3];
        *reinterpret_cast<float4*>(&p[(b0 + bq + r) * NN + j0 + jq]) = o;
    }
}

__global__ void __launch_bounds__(256, 8)
tropical_reduce(const float* __restrict__ bias,
                float* __restrict__ out)
{
    const int i = blockIdx.x * 256 + threadIdx.x;
    float m = g_partials[i];
    #pragma unroll
    for (int s = 1; s < SPLITK; s++)
        m = fminf(m, g_partials[s * (BB * NN) + i]);
    // max_k(x - w) = -min_k(w - x);  out = bias + max = bias - m  (exact)
    out[i] = bias[i & (NN - 1)] - m;
}

extern "C" void kernel_launch(void* const* d_in, const int* in_sizes, int n_in,
                              void* d_out, int out_size) {
    const float* x    = (const float*)d_in[0];   // [128, 1024]
    const float* wgt  = (const float*)d_in[1];   // [1024, 1024]
    const float* bias = (const float*)d_in[2];   // [1024]
    float* out = (float*)d_out;                  // [128, 1024]

    cudaFuncSetAttribute(tropical_main,
                         cudaFuncAttributeMaxDynamicSharedMemorySize, SMEM_BYTES);

    dim3 grid(NN / BN, BB / BM, SPLITK);         // (8, 2, 16) = 256 blocks
    tropical_main<<<grid, NT, SMEM_BYTES>>>(x, wgt);

    const int total = BB * NN;                   // 131072
    tropical_reduce<<<total / 256, 256>>>(bias, out);   // 512 blocks
}